// round 14
// baseline (speedup 1.0000x reference)
#include <cuda_runtime.h>
#include <cuda_bf16.h>

#define PH 7
#define PW 7
#define C_ 256
#define H_ 40
#define W_ 40
#define HW_ (H_ * W_)
#define CPT 8                          // channels per thread (pool)
#define QW  8                          // channel-quads per block
#define POOL_THREADS (PH * PW * QW)    // 392
#define GRID_Y (C_ / (QW * CPT))       // 4

// f32(1/7) and f32(1/3) as XLA's constant-folded reciprocals.
#define RECIP7_BITS 0x3E124925u
#define RECIP3_BITS 0x3EAAAAABu

__constant__ int c_sel[8] = {0, 1, 2, 3, 5, 6, 7, 8};

// Per-(box,bin) windows: x = hs, y = he, z = ws, w = we.
__device__ int4 g_win[4096 * 49];

__device__ __forceinline__ float decode_scalar(const void* p, float dflt)
{
    if (p == nullptr) return dflt;
    unsigned int lo = *(const unsigned int*)p;
    if (lo >= 1u && lo <= 1000000u) return (float)lo;   // int32/int64 low word
    float f = __uint_as_float(lo);
    if (f >= 1.0f && f <= 1.0e6f) return f;             // float32
    return dflt;
}

// ---------------------------------------------------------------------------
// prep_kernel: one block per output box (288). Warp 0 computes the anchor
// box (bit-exact vs R8), writes cat_rois row; threads 0..48 then compute the
// 49 bin windows into g_win.
// ---------------------------------------------------------------------------
__global__ void __launch_bounds__(64)
prep_kernel(const float* __restrict__ rois,
            const void* __restrict__ hh_p,
            const void* __restrict__ hw_p,
            float* __restrict__ out_tail,   // nullptr if no room
            int N)
{
    __shared__ float sbox[4];

    int b = blockIdx.x;
    int t = threadIdx.x;
    int n = b / 9, jj = b % 9;

    if (t < 32) {
        int lane = t;
        float x1 = rois[n * 5 + 1], y1 = rois[n * 5 + 2];
        float x2 = rois[n * 5 + 3], y2 = rois[n * 5 + 4];
        float o0 = 0.0f, o1, o2, o3, o4;

        if (jj == 0) {
            o0 = rois[n * 5 + 0];
            o1 = x1; o2 = y1; o3 = x2; o4 = y2;
        } else {
            float fhh = decode_scalar(hh_p, 640.0f);
            float fhw = decode_scalar(hw_p, 640.0f);
            int m = c_sel[jj - 1];
            float ky = (float)(m / 3), kx = (float)(m % 3);

            float w = __fsub_rn(x2, x1), h = __fsub_rn(y2, y1);
            float cx = __fadd_rn(x1, __fmul_rn(w, __fsub_rn(kx, 0.5f)));
            float cy = __fadd_rn(y1, __fmul_rn(h, __fsub_rn(ky, 0.5f)));
            float w4 = __fmul_rn(w, 0.25f), h4 = __fmul_rn(h, 0.25f);
            float g0 = __fsub_rn(cx, w4), g1 = __fsub_rn(cy, h4);
            float g2 = __fadd_rn(cx, w4), g3 = __fadd_rn(cy, h4);
            float bw = __fadd_rn(__fsub_rn(g2, g0), 1.0f);
            float bh = __fadd_rn(__fsub_rn(g3, g1), 1.0f);
            bool invalid = (g0 < 0.0f) || (g1 < 0.0f) || (g2 >= fhw) || (g3 >= fhh)
                        || (bw < 16.0f) || (bh < 16.0f);
            if (invalid) { g0 = x1; g1 = y1; g2 = x2; g3 = y2; }

            float gwp = __fadd_rn(__fsub_rn(g2, g0), 1.0f);
            float ghp = __fadd_rn(__fsub_rn(g3, g1), 1.0f);
            float gArea = __fmul_rn(gwp, ghp);

            float my_ov = -3.0e38f;
            int my_idx = 0x7fffffff;
            for (int a = lane; a < N; a += 32) {
                float a0 = rois[a * 5 + 1], a1 = rois[a * 5 + 2];
                float a2 = rois[a * 5 + 3], a3 = rois[a * 5 + 4];
                float aw = __fadd_rn(__fsub_rn(a2, a0), 1.0f);
                float ah = __fadd_rn(__fsub_rn(a3, a1), 1.0f);
                float iw = fmaxf(__fadd_rn(__fsub_rn(fminf(a2, g2), fmaxf(a0, g0)), 1.0f), 0.0f);
                float ih = fmaxf(__fadd_rn(__fsub_rn(fminf(a3, g3), fmaxf(a1, g1)), 1.0f), 0.0f);
                float inter = __fmul_rn(iw, ih);
                float uni = __fsub_rn(__fadd_rn(__fmul_rn(aw, ah), gArea), inter);
                float ov = __fdiv_rn(inter, uni);
                if (gwp == 1.0f && ghp == 1.0f) ov = 0.0f;
                if (aw == 1.0f && ah == 1.0f)   ov = -1.0f;
                if (ov > my_ov) { my_ov = ov; my_idx = a; }
            }
            #pragma unroll
            for (int off = 16; off > 0; off >>= 1) {
                float ov2 = __shfl_down_sync(0xffffffffu, my_ov, off);
                int   id2 = __shfl_down_sync(0xffffffffu, my_idx, off);
                if (ov2 > my_ov || (ov2 == my_ov && id2 < my_idx)) {
                    my_ov = ov2; my_idx = id2;
                }
            }
            my_ov  = __shfl_sync(0xffffffffu, my_ov, 0);
            my_idx = __shfl_sync(0xffffffffu, my_idx, 0);

            bool lab = (my_ov >= 0.3f);
            float w_cell = __fsub_rn(g2, g0);
            float h_cell = __fsub_rn(g3, g1);
            float rw = 0.0f, rh = 0.0f;
            if (lab) {
                rw = __fsub_rn(rois[my_idx * 5 + 3], rois[my_idx * 5 + 1]);
                rh = __fsub_rn(rois[my_idx * 5 + 4], rois[my_idx * 5 + 2]);
            }
            bool kill1 = (fmaxf(rw, rh) >= fmaxf(w_cell, h_cell));
            float third = __fmul_rn(fminf(w_cell, h_cell), __uint_as_float(RECIP3_BITS));
            bool kill2 = (fminf(rw, rh) < third);
            lab = lab && (!kill1) && (!kill2);

            if (lab) {
                o1 = rois[my_idx * 5 + 1]; o2 = rois[my_idx * 5 + 2];
                o3 = rois[my_idx * 5 + 3]; o4 = rois[my_idx * 5 + 4];
            } else {
                o1 = g0; o2 = g1; o3 = g2; o4 = g3;
            }
        }

        if (lane == 0) {
            sbox[0] = o1; sbox[1] = o2; sbox[2] = o3; sbox[3] = o4;
            if (out_tail != nullptr) {
                out_tail[b * 5 + 0] = o0;
                out_tail[b * 5 + 1] = o1;
                out_tail[b * 5 + 2] = o2;
                out_tail[b * 5 + 3] = o3;
                out_tail[b * 5 + 4] = o4;
            }
        }
    }
    __syncthreads();

    if (t < 49) {
        int i = t / 7, j = t % 7;

        float x1 = sbox[0], y1 = sbox[1], x2 = sbox[2], y2 = sbox[3];

        float sw = rintf(__fmul_rn(x1, 0.0625f));
        float sh = rintf(__fmul_rn(y1, 0.0625f));
        float ew = rintf(__fmul_rn(x2, 0.0625f));
        float eh = rintf(__fmul_rn(y2, 0.0625f));

        const float r7 = __uint_as_float(RECIP7_BITS);
        float bsh = __fmul_rn(fmaxf(__fadd_rn(__fsub_rn(eh, sh), 1.0f), 1.0f), r7);
        float bsw = __fmul_rn(fmaxf(__fadd_rn(__fsub_rn(ew, sw), 1.0f), 1.0f), r7);

        float hsf = fminf(fmaxf(__fadd_rn(floorf(__fmul_rn((float)i, bsh)), sh), 0.0f), 40.0f);
        float hef = fminf(fmaxf(__fadd_rn(ceilf(__fmul_rn((float)(i + 1), bsh)), sh), 0.0f), 40.0f);
        float wsf = fminf(fmaxf(__fadd_rn(floorf(__fmul_rn((float)j, bsw)), sw), 0.0f), 40.0f);
        float wef = fminf(fmaxf(__fadd_rn(ceilf(__fmul_rn((float)(j + 1), bsw)), sw), 0.0f), 40.0f);

        int4 win;
        win.x = (int)hsf;   // hs
        win.y = (int)hef;   // he
        win.z = (int)wsf;   // ws
        win.w = (int)wef;   // we
        g_win[b * 49 + t] = win;
    }
}

// ---------------------------------------------------------------------------
// pool_kernel: pure streaming, no barriers, no redundant math.
// grid = (288 boxes, 4 channel groups); 392 threads; 8 channels per thread.
// ---------------------------------------------------------------------------
__global__ void __launch_bounds__(POOL_THREADS)
pool_kernel(const float* __restrict__ feat, float* __restrict__ out)
{
    int b = blockIdx.x;
    int t = threadIdx.x;

    int bin = t % 49;
    int q   = t / 49;                              // 0..7
    int c0  = blockIdx.y * (QW * CPT) + q * CPT;   // 8-channel base

    int4 win = g_win[b * 49 + bin];                // L1/L2-hot broadcast
    int hs = win.x, he = win.y, ws = win.z, we = win.w;

    float v[CPT];
    #pragma unroll
    for (int k = 0; k < CPT; k++) v[k] = 0.0f;

    if (he > hs && we > ws) {
        const float* fb = feat + c0 * HW_;
        float m[CPT];
        #pragma unroll
        for (int k = 0; k < CPT; k++) m[k] = -1.0e30f;
        for (int hy = hs; hy < he; ++hy) {
            int base = hy * W_;
            for (int wx = ws; wx < we; ++wx) {
                int o = base + wx;
                #pragma unroll
                for (int k = 0; k < CPT; k++)
                    m[k] = fmaxf(m[k], __ldg(fb + k * HW_ + o));
            }
        }
        #pragma unroll
        for (int k = 0; k < CPT; k++) v[k] = m[k];
    }

    float* ob = out + ((size_t)b * C_ + c0) * 49 + bin;
    #pragma unroll
    for (int k = 0; k < CPT; k++)
        ob[k * 49] = v[k];
}

// ---------------------------------------------------------------------------
extern "C" void kernel_launch(void* const* d_in, const int* in_sizes, int n_in,
                              void* d_out, int out_size)
{
    const float* features = (const float*)d_in[0];
    const float* rois     = (const float*)d_in[1];
    const void*  hh_p     = (n_in > 2) ? d_in[2] : nullptr;
    const void*  hw_p     = (n_in > 3) ? d_in[3] : nullptr;

    int N = in_sizes[1] / 5;              // 32
    int NB = N * 9;                       // 288
    int pool_total = NB * C_ * PH * PW;   // 3,612,672

    float* out = (float*)d_out;
    float* out_tail = (out_size >= pool_total + NB * 5) ? (out + pool_total) : nullptr;

    prep_kernel<<<NB, 64>>>(rois, hh_p, hw_p, out_tail, N);

    dim3 grid(NB, GRID_Y);                // (288, 4)
    pool_kernel<<<grid, POOL_THREADS>>>(features, out);
}

// round 15
// speedup vs baseline: 1.1756x; 1.1756x over previous
#include <cuda_runtime.h>
#include <cuda_bf16.h>

#define PH 7
#define PW 7
#define C_ 256
#define H_ 40
#define W_ 40
#define HW_ (H_ * W_)
#define CPT 4                          // channels per thread per iteration
#define QW  8                          // channel-quads concurrently (t/49)
#define CITER (C_ / (QW * CPT))        // 8 channel-group iterations
#define POOL_THREADS (PH * PW * QW)    // 392

// f32(1/7) and f32(1/3) as XLA's constant-folded reciprocals.
#define RECIP7_BITS 0x3E124925u
#define RECIP3_BITS 0x3EAAAAABu

__constant__ int c_sel[8] = {0, 1, 2, 3, 5, 6, 7, 8};

__device__ __forceinline__ float decode_scalar(const void* p, float dflt)
{
    if (p == nullptr) return dflt;
    unsigned int lo = *(const unsigned int*)p;
    if (lo >= 1u && lo <= 1000000u) return (float)lo;   // int32 / int64 low word
    float f = __uint_as_float(lo);
    if (f >= 1.0f && f <= 1.0e6f) return f;             // float32
    return dflt;
}

// ---------------------------------------------------------------------------
// Fused kernel, one block per output box (288 blocks, 392 threads).
// Phase A (warp 0): anchor box, bit-exact vs R8/R13. Phase B (threads<49):
// bin windows -> smem. Phase C (all): 8 iterations x 4 channels per thread.
// ---------------------------------------------------------------------------
__global__ void __launch_bounds__(POOL_THREADS)
fused_kernel(const float* __restrict__ feat,
             const float* __restrict__ rois,
             const void* __restrict__ hh_p,
             const void* __restrict__ hw_p,
             float* __restrict__ out,
             float* __restrict__ out_tail,   // nullptr if no room
             int N)
{
    __shared__ float sbox[4];
    __shared__ int s_hs[49], s_he[49], s_ws[49], s_we[49];

    int b = blockIdx.x;
    int t = threadIdx.x;
    int n = b / 9, jj = b % 9;

    // ---------------- Phase A: per-box anchor result (warp 0) -------------
    if (t < 32) {
        int lane = t;
        float x1 = rois[n * 5 + 1], y1 = rois[n * 5 + 2];
        float x2 = rois[n * 5 + 3], y2 = rois[n * 5 + 4];
        float o0 = 0.0f, o1, o2, o3, o4;

        if (jj == 0) {
            o0 = rois[n * 5 + 0];
            o1 = x1; o2 = y1; o3 = x2; o4 = y2;
        } else {
            float fhh = decode_scalar(hh_p, 640.0f);
            float fhw = decode_scalar(hw_p, 640.0f);
            int m = c_sel[jj - 1];
            float ky = (float)(m / 3), kx = (float)(m % 3);

            float w = __fsub_rn(x2, x1), h = __fsub_rn(y2, y1);
            float cx = __fadd_rn(x1, __fmul_rn(w, __fsub_rn(kx, 0.5f)));
            float cy = __fadd_rn(y1, __fmul_rn(h, __fsub_rn(ky, 0.5f)));
            float w4 = __fmul_rn(w, 0.25f), h4 = __fmul_rn(h, 0.25f);
            float g0 = __fsub_rn(cx, w4), g1 = __fsub_rn(cy, h4);
            float g2 = __fadd_rn(cx, w4), g3 = __fadd_rn(cy, h4);
            float bw = __fadd_rn(__fsub_rn(g2, g0), 1.0f);
            float bh = __fadd_rn(__fsub_rn(g3, g1), 1.0f);
            bool invalid = (g0 < 0.0f) || (g1 < 0.0f) || (g2 >= fhw) || (g3 >= fhh)
                        || (bw < 16.0f) || (bh < 16.0f);
            if (invalid) { g0 = x1; g1 = y1; g2 = x2; g3 = y2; }

            float gwp = __fadd_rn(__fsub_rn(g2, g0), 1.0f);
            float ghp = __fadd_rn(__fsub_rn(g3, g1), 1.0f);
            float gArea = __fmul_rn(gwp, ghp);

            float my_ov = -3.0e38f;
            int my_idx = 0x7fffffff;
            for (int a = lane; a < N; a += 32) {
                float a0 = rois[a * 5 + 1], a1 = rois[a * 5 + 2];
                float a2 = rois[a * 5 + 3], a3 = rois[a * 5 + 4];
                float aw = __fadd_rn(__fsub_rn(a2, a0), 1.0f);
                float ah = __fadd_rn(__fsub_rn(a3, a1), 1.0f);
                float iw = fmaxf(__fadd_rn(__fsub_rn(fminf(a2, g2), fmaxf(a0, g0)), 1.0f), 0.0f);
                float ih = fmaxf(__fadd_rn(__fsub_rn(fminf(a3, g3), fmaxf(a1, g1)), 1.0f), 0.0f);
                float inter = __fmul_rn(iw, ih);
                float uni = __fsub_rn(__fadd_rn(__fmul_rn(aw, ah), gArea), inter);
                float ov = __fdiv_rn(inter, uni);
                if (gwp == 1.0f && ghp == 1.0f) ov = 0.0f;
                if (aw == 1.0f && ah == 1.0f)   ov = -1.0f;
                if (ov > my_ov) { my_ov = ov; my_idx = a; }
            }
            #pragma unroll
            for (int off = 16; off > 0; off >>= 1) {
                float ov2 = __shfl_down_sync(0xffffffffu, my_ov, off);
                int   id2 = __shfl_down_sync(0xffffffffu, my_idx, off);
                if (ov2 > my_ov || (ov2 == my_ov && id2 < my_idx)) {
                    my_ov = ov2; my_idx = id2;
                }
            }
            my_ov  = __shfl_sync(0xffffffffu, my_ov, 0);
            my_idx = __shfl_sync(0xffffffffu, my_idx, 0);

            bool lab = (my_ov >= 0.3f);
            float w_cell = __fsub_rn(g2, g0);
            float h_cell = __fsub_rn(g3, g1);
            float rw = 0.0f, rh = 0.0f;
            if (lab) {
                rw = __fsub_rn(rois[my_idx * 5 + 3], rois[my_idx * 5 + 1]);
                rh = __fsub_rn(rois[my_idx * 5 + 4], rois[my_idx * 5 + 2]);
            }
            bool kill1 = (fmaxf(rw, rh) >= fmaxf(w_cell, h_cell));
            float third = __fmul_rn(fminf(w_cell, h_cell), __uint_as_float(RECIP3_BITS));
            bool kill2 = (fminf(rw, rh) < third);
            lab = lab && (!kill1) && (!kill2);

            if (lab) {
                o1 = rois[my_idx * 5 + 1]; o2 = rois[my_idx * 5 + 2];
                o3 = rois[my_idx * 5 + 3]; o4 = rois[my_idx * 5 + 4];
            } else {
                o1 = g0; o2 = g1; o3 = g2; o4 = g3;
            }
        }

        if (lane == 0) {
            sbox[0] = o1; sbox[1] = o2; sbox[2] = o3; sbox[3] = o4;
            if (out_tail != nullptr) {
                out_tail[b * 5 + 0] = o0;
                out_tail[b * 5 + 1] = o1;
                out_tail[b * 5 + 2] = o2;
                out_tail[b * 5 + 3] = o3;
                out_tail[b * 5 + 4] = o4;
            }
        }
    }
    __syncthreads();

    // ---------------- Phase B: 49 bin windows (threads 0..48) -------------
    if (t < 49) {
        int i = t / 7, j = t % 7;

        float x1 = sbox[0], y1 = sbox[1], x2 = sbox[2], y2 = sbox[3];

        float sw = rintf(__fmul_rn(x1, 0.0625f));
        float sh = rintf(__fmul_rn(y1, 0.0625f));
        float ew = rintf(__fmul_rn(x2, 0.0625f));
        float eh = rintf(__fmul_rn(y2, 0.0625f));

        const float r7 = __uint_as_float(RECIP7_BITS);
        float bsh = __fmul_rn(fmaxf(__fadd_rn(__fsub_rn(eh, sh), 1.0f), 1.0f), r7);
        float bsw = __fmul_rn(fmaxf(__fadd_rn(__fsub_rn(ew, sw), 1.0f), 1.0f), r7);

        float hsf = fminf(fmaxf(__fadd_rn(floorf(__fmul_rn((float)i, bsh)), sh), 0.0f), 40.0f);
        float hef = fminf(fmaxf(__fadd_rn(ceilf(__fmul_rn((float)(i + 1), bsh)), sh), 0.0f), 40.0f);
        float wsf = fminf(fmaxf(__fadd_rn(floorf(__fmul_rn((float)j, bsw)), sw), 0.0f), 40.0f);
        float wef = fminf(fmaxf(__fadd_rn(ceilf(__fmul_rn((float)(j + 1), bsw)), sw), 0.0f), 40.0f);

        s_hs[t] = (int)hsf;
        s_he[t] = (int)hef;
        s_ws[t] = (int)wsf;
        s_we[t] = (int)wef;
    }
    __syncthreads();

    // ---------------- Phase C: 8 iterations x 4 channels per thread -------
    int bin = t % 49;
    int q   = t / 49;                     // 0..7

    int hs = s_hs[bin], he = s_he[bin];
    int ws = s_ws[bin], we = s_we[bin];
    bool nonempty = (he > hs) && (we > ws);

    #pragma unroll
    for (int it = 0; it < CITER; ++it) {
        int c0 = (it * QW + q) * CPT;

        float v0 = 0.0f, v1 = 0.0f, v2 = 0.0f, v3 = 0.0f;
        if (nonempty) {
            const float* fb = feat + c0 * HW_;
            float m0 = -1.0e30f, m1 = -1.0e30f, m2 = -1.0e30f, m3 = -1.0e30f;
            for (int hy = hs; hy < he; ++hy) {
                int base = hy * W_;
                for (int wx = ws; wx < we; ++wx) {
                    int o = base + wx;
                    m0 = fmaxf(m0, __ldg(fb + 0 * HW_ + o));
                    m1 = fmaxf(m1, __ldg(fb + 1 * HW_ + o));
                    m2 = fmaxf(m2, __ldg(fb + 2 * HW_ + o));
                    m3 = fmaxf(m3, __ldg(fb + 3 * HW_ + o));
                }
            }
            v0 = m0; v1 = m1; v2 = m2; v3 = m3;
        }

        float* ob = out + ((size_t)b * C_ + c0) * 49 + bin;
        ob[0 * 49] = v0;
        ob[1 * 49] = v1;
        ob[2 * 49] = v2;
        ob[3 * 49] = v3;
    }
}

// ---------------------------------------------------------------------------
extern "C" void kernel_launch(void* const* d_in, const int* in_sizes, int n_in,
                              void* d_out, int out_size)
{
    const float* features = (const float*)d_in[0];
    const float* rois     = (const float*)d_in[1];
    const void*  hh_p     = (n_in > 2) ? d_in[2] : nullptr;
    const void*  hw_p     = (n_in > 3) ? d_in[3] : nullptr;

    int N = in_sizes[1] / 5;              // 32
    int NB = N * 9;                       // 288
    int pool_total = NB * C_ * PH * PW;   // 3,612,672

    float* out = (float*)d_out;
    float* out_tail = (out_size >= pool_total + NB * 5) ? (out + pool_total) : nullptr;

    fused_kernel<<<NB, POOL_THREADS>>>(features, rois, hh_p, hw_p,
                                       out, out_tail, N);
}

// round 16
// speedup vs baseline: 1.2946x; 1.1012x over previous
#include <cuda_runtime.h>
#include <cuda_bf16.h>

#define PH 7
#define PW 7
#define C_ 256
#define H_ 40
#define W_ 40
#define HW_ (H_ * W_)
#define CPT 4                          // channels per thread
#define QW  8                          // channel-quads per block
#define ACTIVE_THREADS (PH * PW * QW)  // 392
#define BLOCK_THREADS 416              // 13 full warps
#define GRID_Y (C_ / (QW * CPT))       // 8

// f32(1/7) and f32(1/3) as XLA's constant-folded reciprocals.
#define RECIP7_BITS 0x3E124925u
#define RECIP3_BITS 0x3EAAAAABu

__constant__ int c_sel[8] = {0, 1, 2, 3, 5, 6, 7, 8};

__device__ __forceinline__ float decode_scalar(const void* p, float dflt)
{
    if (p == nullptr) return dflt;
    unsigned int lo = *(const unsigned int*)p;
    if (lo >= 1u && lo <= 1000000u) return (float)lo;   // int32 / int64 low word
    float f = __uint_as_float(lo);
    if (f >= 1.0f && f <= 1.0e6f) return f;             // float32
    return dflt;
}

// ---------------------------------------------------------------------------
// Fully barrier-free fused kernel. grid = (288 boxes, 8 channel groups),
// 416 threads (13 warps). Every warp computes the anchor independently
// (lane = roi, shfl argmax with first-occurrence tie-break); every thread
// then computes its own bin window and pools 4 channels. No __syncthreads.
// ---------------------------------------------------------------------------
__global__ void __launch_bounds__(BLOCK_THREADS)
fused_kernel(const float* __restrict__ feat,
             const float* __restrict__ rois,
             const void* __restrict__ hh_p,
             const void* __restrict__ hw_p,
             float* __restrict__ out,
             float* __restrict__ out_tail,   // nullptr if no room
             int N)
{
    int b = blockIdx.x;
    int t = threadIdx.x;
    int lane = t & 31;
    int n = b / 9, jj = b % 9;

    // ---------------- Phase A: anchor box, computed per-warp --------------
    float x1 = rois[n * 5 + 1], y1 = rois[n * 5 + 2];
    float x2 = rois[n * 5 + 3], y2 = rois[n * 5 + 4];
    float o1, o2, o3, o4;

    if (jj == 0) {
        o1 = x1; o2 = y1; o3 = x2; o4 = y2;
    } else {
        float fhh = decode_scalar(hh_p, 640.0f);
        float fhw = decode_scalar(hw_p, 640.0f);
        int m = c_sel[jj - 1];
        float ky = (float)(m / 3), kx = (float)(m % 3);

        float w = __fsub_rn(x2, x1), h = __fsub_rn(y2, y1);
        float cx = __fadd_rn(x1, __fmul_rn(w, __fsub_rn(kx, 0.5f)));
        float cy = __fadd_rn(y1, __fmul_rn(h, __fsub_rn(ky, 0.5f)));
        float w4 = __fmul_rn(w, 0.25f), h4 = __fmul_rn(h, 0.25f);
        float g0 = __fsub_rn(cx, w4), g1 = __fsub_rn(cy, h4);
        float g2 = __fadd_rn(cx, w4), g3 = __fadd_rn(cy, h4);
        float bw = __fadd_rn(__fsub_rn(g2, g0), 1.0f);
        float bh = __fadd_rn(__fsub_rn(g3, g1), 1.0f);
        bool invalid = (g0 < 0.0f) || (g1 < 0.0f) || (g2 >= fhw) || (g3 >= fhh)
                    || (bw < 16.0f) || (bh < 16.0f);
        if (invalid) { g0 = x1; g1 = y1; g2 = x2; g3 = y2; }

        float gwp = __fadd_rn(__fsub_rn(g2, g0), 1.0f);
        float ghp = __fadd_rn(__fsub_rn(g3, g1), 1.0f);
        float gArea = __fmul_rn(gwp, ghp);

        // lane a handles roi a (N==32 -> one per lane; loop kept for safety)
        float my_ov = -3.0e38f;
        int my_idx = 0x7fffffff;
        for (int a = lane; a < N; a += 32) {
            float a0 = rois[a * 5 + 1], a1 = rois[a * 5 + 2];
            float a2 = rois[a * 5 + 3], a3 = rois[a * 5 + 4];
            float aw = __fadd_rn(__fsub_rn(a2, a0), 1.0f);
            float ah = __fadd_rn(__fsub_rn(a3, a1), 1.0f);
            float iw = fmaxf(__fadd_rn(__fsub_rn(fminf(a2, g2), fmaxf(a0, g0)), 1.0f), 0.0f);
            float ih = fmaxf(__fadd_rn(__fsub_rn(fminf(a3, g3), fmaxf(a1, g1)), 1.0f), 0.0f);
            float inter = __fmul_rn(iw, ih);
            float uni = __fsub_rn(__fadd_rn(__fmul_rn(aw, ah), gArea), inter);
            float ov = __fdiv_rn(inter, uni);
            if (gwp == 1.0f && ghp == 1.0f) ov = 0.0f;
            if (aw == 1.0f && ah == 1.0f)   ov = -1.0f;
            if (ov > my_ov) { my_ov = ov; my_idx = a; }
        }
        // Warp argmax, first-occurrence tie-break (lower index wins).
        #pragma unroll
        for (int off = 16; off > 0; off >>= 1) {
            float ov2 = __shfl_down_sync(0xffffffffu, my_ov, off);
            int   id2 = __shfl_down_sync(0xffffffffu, my_idx, off);
            if (ov2 > my_ov || (ov2 == my_ov && id2 < my_idx)) {
                my_ov = ov2; my_idx = id2;
            }
        }
        my_ov  = __shfl_sync(0xffffffffu, my_ov, 0);
        my_idx = __shfl_sync(0xffffffffu, my_idx, 0);

        bool lab = (my_ov >= 0.3f);
        float w_cell = __fsub_rn(g2, g0);
        float h_cell = __fsub_rn(g3, g1);
        float rw = 0.0f, rh = 0.0f;
        if (lab) {
            rw = __fsub_rn(rois[my_idx * 5 + 3], rois[my_idx * 5 + 1]);
            rh = __fsub_rn(rois[my_idx * 5 + 4], rois[my_idx * 5 + 2]);
        }
        bool kill1 = (fmaxf(rw, rh) >= fmaxf(w_cell, h_cell));
        float third = __fmul_rn(fminf(w_cell, h_cell), __uint_as_float(RECIP3_BITS));
        bool kill2 = (fminf(rw, rh) < third);
        lab = lab && (!kill1) && (!kill2);

        if (lab) {
            o1 = rois[my_idx * 5 + 1]; o2 = rois[my_idx * 5 + 2];
            o3 = rois[my_idx * 5 + 3]; o4 = rois[my_idx * 5 + 4];
        } else {
            o1 = g0; o2 = g1; o3 = g2; o4 = g3;
        }
    }

    // cat_rois tail: one thread of one block per box.
    if (t == 0 && blockIdx.y == 0 && out_tail != nullptr) {
        out_tail[b * 5 + 0] = (jj == 0) ? rois[n * 5 + 0] : 0.0f;
        out_tail[b * 5 + 1] = o1;
        out_tail[b * 5 + 2] = o2;
        out_tail[b * 5 + 3] = o3;
        out_tail[b * 5 + 4] = o4;
    }

    if (t >= ACTIVE_THREADS) return;   // whole-warp exit for warp 12's tail

    // ---------------- Phase B: this thread's bin window -------------------
    int bin = t % 49;
    int q   = t / 49;                     // 0..7
    int i = bin / 7, j = bin % 7;

    float sw = rintf(__fmul_rn(o1, 0.0625f));
    float sh = rintf(__fmul_rn(o2, 0.0625f));
    float ew = rintf(__fmul_rn(o3, 0.0625f));
    float eh = rintf(__fmul_rn(o4, 0.0625f));

    const float r7 = __uint_as_float(RECIP7_BITS);
    float bsh = __fmul_rn(fmaxf(__fadd_rn(__fsub_rn(eh, sh), 1.0f), 1.0f), r7);
    float bsw = __fmul_rn(fmaxf(__fadd_rn(__fsub_rn(ew, sw), 1.0f), 1.0f), r7);

    float hsf = fminf(fmaxf(__fadd_rn(floorf(__fmul_rn((float)i, bsh)), sh), 0.0f), 40.0f);
    float hef = fminf(fmaxf(__fadd_rn(ceilf(__fmul_rn((float)(i + 1), bsh)), sh), 0.0f), 40.0f);
    float wsf = fminf(fmaxf(__fadd_rn(floorf(__fmul_rn((float)j, bsw)), sw), 0.0f), 40.0f);
    float wef = fminf(fmaxf(__fadd_rn(ceilf(__fmul_rn((float)(j + 1), bsw)), sw), 0.0f), 40.0f);

    int hs = (int)hsf, he = (int)hef, ws = (int)wsf, we = (int)wef;

    // ---------------- Phase C: pool 4 channels ----------------------------
    int c0 = blockIdx.y * (QW * CPT) + q * CPT;

    float v0 = 0.0f, v1 = 0.0f, v2 = 0.0f, v3 = 0.0f;
    if (he > hs && we > ws) {
        const float* fb = feat + c0 * HW_;
        float m0 = -1.0e30f, m1 = -1.0e30f, m2 = -1.0e30f, m3 = -1.0e30f;
        for (int hy = hs; hy < he; ++hy) {
            int base = hy * W_;
            for (int wx = ws; wx < we; ++wx) {
                int o = base + wx;
                m0 = fmaxf(m0, __ldg(fb + 0 * HW_ + o));
                m1 = fmaxf(m1, __ldg(fb + 1 * HW_ + o));
                m2 = fmaxf(m2, __ldg(fb + 2 * HW_ + o));
                m3 = fmaxf(m3, __ldg(fb + 3 * HW_ + o));
            }
        }
        v0 = m0; v1 = m1; v2 = m2; v3 = m3;
    }

    float* ob = out + ((size_t)b * C_ + c0) * 49 + bin;
    ob[0 * 49] = v0;
    ob[1 * 49] = v1;
    ob[2 * 49] = v2;
    ob[3 * 49] = v3;
}

// ---------------------------------------------------------------------------
extern "C" void kernel_launch(void* const* d_in, const int* in_sizes, int n_in,
                              void* d_out, int out_size)
{
    const float* features = (const float*)d_in[0];
    const float* rois     = (const float*)d_in[1];
    const void*  hh_p     = (n_in > 2) ? d_in[2] : nullptr;
    const void*  hw_p     = (n_in > 3) ? d_in[3] : nullptr;

    int N = in_sizes[1] / 5;              // 32
    int NB = N * 9;                       // 288
    int pool_total = NB * C_ * PH * PW;   // 3,612,672

    float* out = (float*)d_out;
    float* out_tail = (out_size >= pool_total + NB * 5) ? (out + pool_total) : nullptr;

    dim3 grid(NB, GRID_Y);                // (288, 8) = 2304 blocks
    fused_kernel<<<grid, BLOCK_THREADS>>>(features, rois, hh_p, hw_p,
                                          out, out_tail, N);
}

// round 17
// speedup vs baseline: 1.5989x; 1.2351x over previous
#include <cuda_runtime.h>
#include <cuda_bf16.h>

#define PH 7
#define PW 7
#define C_ 256
#define H_ 40
#define W_ 40
#define HW_ (H_ * W_)
#define CPT 4                          // channels per thread (pool)
#define QW  8                          // channel-quads per block
#define POOL_THREADS (PH * PW * QW)    // 392
#define GRID_Y (C_ / (QW * CPT))       // 8

// f32(1/7) and f32(1/3) as XLA's constant-folded reciprocals.
#define RECIP7_BITS 0x3E124925u
#define RECIP3_BITS 0x3EAAAAABu

__constant__ int c_sel[8] = {0, 1, 2, 3, 5, 6, 7, 8};

// Per-(box,bin) windows: x = hs, y = he, z = ws, w = we.
__device__ int4 g_win[4096 * 49];

__device__ __forceinline__ float decode_scalar(const void* p, float dflt)
{
    if (p == nullptr) return dflt;
    unsigned int lo = *(const unsigned int*)p;
    if (lo >= 1u && lo <= 1000000u) return (float)lo;   // int32 / int64 low word
    float f = __uint_as_float(lo);
    if (f >= 1.0f && f <= 1.0e6f) return f;             // float32
    return dflt;
}

// ---------------------------------------------------------------------------
// prep_kernel: one block per output box (288, 64 threads). Warp 0 computes
// the anchor box (bit-exact vs R8/R13), writes the cat_rois tail row;
// threads 0..48 then compute the 49 bin windows into g_win.
// ---------------------------------------------------------------------------
__global__ void __launch_bounds__(64)
prep_kernel(const float* __restrict__ rois,
            const void* __restrict__ hh_p,
            const void* __restrict__ hw_p,
            float* __restrict__ out_tail,   // nullptr if no room
            int N)
{
    __shared__ float sbox[4];

    int b = blockIdx.x;
    int t = threadIdx.x;
    int n = b / 9, jj = b % 9;

    if (t < 32) {
        int lane = t;
        float x1 = rois[n * 5 + 1], y1 = rois[n * 5 + 2];
        float x2 = rois[n * 5 + 3], y2 = rois[n * 5 + 4];
        float o0 = 0.0f, o1, o2, o3, o4;

        if (jj == 0) {
            o0 = rois[n * 5 + 0];
            o1 = x1; o2 = y1; o3 = x2; o4 = y2;
        } else {
            float fhh = decode_scalar(hh_p, 640.0f);
            float fhw = decode_scalar(hw_p, 640.0f);
            int m = c_sel[jj - 1];
            float ky = (float)(m / 3), kx = (float)(m % 3);

            float w = __fsub_rn(x2, x1), h = __fsub_rn(y2, y1);
            float cx = __fadd_rn(x1, __fmul_rn(w, __fsub_rn(kx, 0.5f)));
            float cy = __fadd_rn(y1, __fmul_rn(h, __fsub_rn(ky, 0.5f)));
            float w4 = __fmul_rn(w, 0.25f), h4 = __fmul_rn(h, 0.25f);
            float g0 = __fsub_rn(cx, w4), g1 = __fsub_rn(cy, h4);
            float g2 = __fadd_rn(cx, w4), g3 = __fadd_rn(cy, h4);
            float bw = __fadd_rn(__fsub_rn(g2, g0), 1.0f);
            float bh = __fadd_rn(__fsub_rn(g3, g1), 1.0f);
            bool invalid = (g0 < 0.0f) || (g1 < 0.0f) || (g2 >= fhw) || (g3 >= fhh)
                        || (bw < 16.0f) || (bh < 16.0f);
            if (invalid) { g0 = x1; g1 = y1; g2 = x2; g3 = y2; }

            float gwp = __fadd_rn(__fsub_rn(g2, g0), 1.0f);
            float ghp = __fadd_rn(__fsub_rn(g3, g1), 1.0f);
            float gArea = __fmul_rn(gwp, ghp);

            float my_ov = -3.0e38f;
            int my_idx = 0x7fffffff;
            for (int a = lane; a < N; a += 32) {
                float a0 = rois[a * 5 + 1], a1 = rois[a * 5 + 2];
                float a2 = rois[a * 5 + 3], a3 = rois[a * 5 + 4];
                float aw = __fadd_rn(__fsub_rn(a2, a0), 1.0f);
                float ah = __fadd_rn(__fsub_rn(a3, a1), 1.0f);
                float iw = fmaxf(__fadd_rn(__fsub_rn(fminf(a2, g2), fmaxf(a0, g0)), 1.0f), 0.0f);
                float ih = fmaxf(__fadd_rn(__fsub_rn(fminf(a3, g3), fmaxf(a1, g1)), 1.0f), 0.0f);
                float inter = __fmul_rn(iw, ih);
                float uni = __fsub_rn(__fadd_rn(__fmul_rn(aw, ah), gArea), inter);
                float ov = __fdiv_rn(inter, uni);
                if (gwp == 1.0f && ghp == 1.0f) ov = 0.0f;
                if (aw == 1.0f && ah == 1.0f)   ov = -1.0f;
                if (ov > my_ov) { my_ov = ov; my_idx = a; }
            }
            #pragma unroll
            for (int off = 16; off > 0; off >>= 1) {
                float ov2 = __shfl_down_sync(0xffffffffu, my_ov, off);
                int   id2 = __shfl_down_sync(0xffffffffu, my_idx, off);
                if (ov2 > my_ov || (ov2 == my_ov && id2 < my_idx)) {
                    my_ov = ov2; my_idx = id2;
                }
            }
            my_ov  = __shfl_sync(0xffffffffu, my_ov, 0);
            my_idx = __shfl_sync(0xffffffffu, my_idx, 0);

            bool lab = (my_ov >= 0.3f);
            float w_cell = __fsub_rn(g2, g0);
            float h_cell = __fsub_rn(g3, g1);
            float rw = 0.0f, rh = 0.0f;
            if (lab) {
                rw = __fsub_rn(rois[my_idx * 5 + 3], rois[my_idx * 5 + 1]);
                rh = __fsub_rn(rois[my_idx * 5 + 4], rois[my_idx * 5 + 2]);
            }
            bool kill1 = (fmaxf(rw, rh) >= fmaxf(w_cell, h_cell));
            float third = __fmul_rn(fminf(w_cell, h_cell), __uint_as_float(RECIP3_BITS));
            bool kill2 = (fminf(rw, rh) < third);
            lab = lab && (!kill1) && (!kill2);

            if (lab) {
                o1 = rois[my_idx * 5 + 1]; o2 = rois[my_idx * 5 + 2];
                o3 = rois[my_idx * 5 + 3]; o4 = rois[my_idx * 5 + 4];
            } else {
                o1 = g0; o2 = g1; o3 = g2; o4 = g3;
            }
        }

        if (lane == 0) {
            sbox[0] = o1; sbox[1] = o2; sbox[2] = o3; sbox[3] = o4;
            if (out_tail != nullptr) {
                out_tail[b * 5 + 0] = o0;
                out_tail[b * 5 + 1] = o1;
                out_tail[b * 5 + 2] = o2;
                out_tail[b * 5 + 3] = o3;
                out_tail[b * 5 + 4] = o4;
            }
        }
    }
    __syncthreads();

    if (t < 49) {
        int i = t / 7, j = t % 7;

        float x1 = sbox[0], y1 = sbox[1], x2 = sbox[2], y2 = sbox[3];

        float sw = rintf(__fmul_rn(x1, 0.0625f));
        float sh = rintf(__fmul_rn(y1, 0.0625f));
        float ew = rintf(__fmul_rn(x2, 0.0625f));
        float eh = rintf(__fmul_rn(y2, 0.0625f));

        const float r7 = __uint_as_float(RECIP7_BITS);
        float bsh = __fmul_rn(fmaxf(__fadd_rn(__fsub_rn(eh, sh), 1.0f), 1.0f), r7);
        float bsw = __fmul_rn(fmaxf(__fadd_rn(__fsub_rn(ew, sw), 1.0f), 1.0f), r7);

        float hsf = fminf(fmaxf(__fadd_rn(floorf(__fmul_rn((float)i, bsh)), sh), 0.0f), 40.0f);
        float hef = fminf(fmaxf(__fadd_rn(ceilf(__fmul_rn((float)(i + 1), bsh)), sh), 0.0f), 40.0f);
        float wsf = fminf(fmaxf(__fadd_rn(floorf(__fmul_rn((float)j, bsw)), sw), 0.0f), 40.0f);
        float wef = fminf(fmaxf(__fadd_rn(ceilf(__fmul_rn((float)(j + 1), bsw)), sw), 0.0f), 40.0f);

        int4 win;
        win.x = (int)hsf;   // hs
        win.y = (int)hef;   // he
        win.z = (int)wsf;   // ws
        win.w = (int)wef;   // we
        g_win[b * 49 + t] = win;
    }
}

// ---------------------------------------------------------------------------
// pool_kernel: pure streaming, no barriers, no redundant math, CPT=4.
// grid = (288 boxes, 8 channel groups); 392 threads.
// ---------------------------------------------------------------------------
__global__ void __launch_bounds__(POOL_THREADS)
pool_kernel(const float* __restrict__ feat, float* __restrict__ out)
{
    int b = blockIdx.x;
    int t = threadIdx.x;

    int bin = t % 49;
    int q   = t / 49;                              // 0..7
    int c0  = blockIdx.y * (QW * CPT) + q * CPT;   // 4-channel base

    int4 win = g_win[b * 49 + bin];                // L1/L2-hot broadcast
    int hs = win.x, he = win.y, ws = win.z, we = win.w;

    float v0 = 0.0f, v1 = 0.0f, v2 = 0.0f, v3 = 0.0f;
    if (he > hs && we > ws) {
        const float* fb = feat + c0 * HW_;
        float m0 = -1.0e30f, m1 = -1.0e30f, m2 = -1.0e30f, m3 = -1.0e30f;
        for (int hy = hs; hy < he; ++hy) {
            int base = hy * W_;
            for (int wx = ws; wx < we; ++wx) {
                int o = base + wx;
                m0 = fmaxf(m0, __ldg(fb + 0 * HW_ + o));
                m1 = fmaxf(m1, __ldg(fb + 1 * HW_ + o));
                m2 = fmaxf(m2, __ldg(fb + 2 * HW_ + o));
                m3 = fmaxf(m3, __ldg(fb + 3 * HW_ + o));
            }
        }
        v0 = m0; v1 = m1; v2 = m2; v3 = m3;
    }

    float* ob = out + ((size_t)b * C_ + c0) * 49 + bin;
    ob[0 * 49] = v0;
    ob[1 * 49] = v1;
    ob[2 * 49] = v2;
    ob[3 * 49] = v3;
}

// ---------------------------------------------------------------------------
extern "C" void kernel_launch(void* const* d_in, const int* in_sizes, int n_in,
                              void* d_out, int out_size)
{
    const float* features = (const float*)d_in[0];
    const float* rois     = (const float*)d_in[1];
    const void*  hh_p     = (n_in > 2) ? d_in[2] : nullptr;
    const void*  hw_p     = (n_in > 3) ? d_in[3] : nullptr;

    int N = in_sizes[1] / 5;              // 32
    int NB = N * 9;                       // 288
    int pool_total = NB * C_ * PH * PW;   // 3,612,672

    float* out = (float*)d_out;
    float* out_tail = (out_size >= pool_total + NB * 5) ? (out + pool_total) : nullptr;

    prep_kernel<<<NB, 64>>>(rois, hh_p, hw_p, out_tail, N);

    dim3 grid(NB, GRID_Y);                // (288, 8) = 2304 blocks
    pool_kernel<<<grid, POOL_THREADS>>>(features, out);
}